// round 15
// baseline (speedup 1.0000x reference)
#include <cuda_runtime.h>
#include <stdint.h>

// out[s] = float(in[0] ^ ... ^ in[s]), in: [4096, 8192] int32 0/1, out float32.
// Single-pass decoupled-lookback XOR scan. R15: barrier-free data path.
//  - R14 geometry: NTILE=64 x LANES=32 (warp-wide), GRPS=16 data warps, VPT=8,
//    128 rows/chunk, NCHUNK=32, NBLOCKS=2048, +1 lookback warp (544 thr).
//  - NO block-wide barrier after the ticket broadcast. Warps coordinate via a
//    smem readiness bitmask: bit g = warp g's lane-aggregates in smem,
//    bit 16 = exclusive prefix (exc) ready. Warp g spins on bits <g | EXCBIT,
//    then streams its stores. Loads/stores of different warps fully overlap.
//  - Warp 15 publishes g_agg gated ONLY on mask (never on exc) so the
//    cross-block aggregate chain stays load-bound; publishes g_inc once exc
//    arrives. Lookback warp walks predecessors concurrently with all loads.
//  - epoch-encoded flags (replay-safe), same-thread release/acquire ordering.

#define SEQ      4096
#define COLS_I32 8192
#define ROW_I4   (COLS_I32 / 4)          // 2048 int4 per row

#define NTILE    64
#define LANES    32                      // one warp wide
#define GRPS     16                      // data warps
#define VPT      8
#define ROWS_PER_CHUNK (GRPS * VPT)      // 128
#define NCHUNK   (SEQ / ROWS_PER_CHUNK)  // 32
#define DATA_THREADS (LANES * GRPS)      // 512
#define THREADS  (DATA_THREADS + 32)     // 544
#define NBLOCKS  (NTILE * NCHUNK)        // 2048 = 2^11
#define EXCBIT   (1 << 16)

__device__ int4         g_agg[(size_t)NTILE * NCHUNK * LANES];   // 1 MB
__device__ int4         g_inc[(size_t)NTILE * NCHUNK * LANES];   // 1 MB
__device__ int          g_flags[NTILE * NCHUNK * LANES];         // 256 KB
__device__ unsigned int g_ticket;                                // never reset

__device__ __forceinline__ int4 x4(int4 a, int4 b) {
    a.x ^= b.x; a.y ^= b.y; a.z ^= b.z; a.w ^= b.w; return a;
}
__device__ __forceinline__ int ld_acq(const int* p) {
    int v;
    asm volatile("ld.acquire.gpu.global.b32 %0, [%1];" : "=r"(v) : "l"(p) : "memory");
    return v;
}
__device__ __forceinline__ void st_rel(int* p, int v) {
    asm volatile("st.release.gpu.global.b32 [%0], %1;" :: "l"(p), "r"(v) : "memory");
}
__device__ __forceinline__ float4 tofloat01(int4 r) {
    float4 f;
    f.x = __int_as_float(r.x * 0x3f800000);
    f.y = __int_as_float(r.y * 0x3f800000);
    f.z = __int_as_float(r.z * 0x3f800000);
    f.w = __int_as_float(r.w * 0x3f800000);
    return f;
}

__global__ __launch_bounds__(THREADS, 2)
void xorscan_kernel(const int4* __restrict__ in, float4* __restrict__ out) {
    __shared__ unsigned int sh_ticket;
    __shared__ int          sh_mask;       // bits 0..15: warp aggs; bit16: exc
    __shared__ int4 sh_agg[GRPS][LANES];   // 8 KB
    __shared__ int4 sh_exc[LANES];         // 512 B

    const int tid = threadIdx.x;
    if (tid == 0) {
        sh_mask = 0;
        sh_ticket = atomicAdd(&g_ticket, 1u);
    }
    __syncthreads();                       // the ONLY block-wide barrier
    const unsigned int ticket = sh_ticket;
    const unsigned int lt     = ticket & (NBLOCKS - 1);
    const int epoch2 = (int)((ticket >> 11) * 2u);
    const int tile   = (int)(lt & (NTILE - 1));          // fill all tiles first
    const int chunk  = (int)(lt >> 6);                   // NTILE = 64

    const int lane = tid & (LANES - 1);
    const int grp  = tid >> 5;                           // 0..16

    volatile int* vmask = &sh_mask;

    if (grp == GRPS) {
        // ---------- lookback warp: concurrent with all data-warp loads ----------
        int4 exc = make_int4(0, 0, 0, 0);
        if (chunk > 0) {
            int look = chunk - 1;
            while (true) {
                const size_t pidx = (size_t)(tile * NCHUNK + look) * LANES + lane;
                int s;
                do { s = ld_acq(&g_flags[pidx]); } while (s <= epoch2);
                if (s == epoch2 + 2) { exc = x4(exc, __ldcg(&g_inc[pidx])); break; }
                exc = x4(exc, __ldcg(&g_agg[pidx]));
                look--;
            }
        }
        sh_exc[lane] = exc;
        __threadfence_block();
        __syncwarp();
        if (lane == 0) atomicOr(&sh_mask, EXCBIT);
        return;
    }

    // ---------------- data warps (no block barriers below) ----------------
    const long row0 = (long)chunk * ROWS_PER_CHUNK + (long)grp * VPT;
    const long base = row0 * ROW_I4 + (long)tile * LANES + lane;

    int4 v[VPT];
#pragma unroll
    for (int i = 0; i < VPT; i++) v[i] = __ldcs(&in[base + (long)i * ROW_I4]);
#pragma unroll
    for (int i = 1; i < VPT; i++) v[i] = x4(v[i], v[i - 1]);

    // publish this warp's per-lane aggregate (warp width == LANES: no reduce)
    sh_agg[grp][lane] = v[VPT - 1];
    __threadfence_block();
    __syncwarp();
    if (lane == 0) atomicOr(&sh_mask, 1 << grp);

    // wait for predecessors' aggregates (NOT exc yet)
    const int need_pred = (1 << grp) - 1;
    while ((*vmask & need_pred) != need_pred) { }
    __threadfence_block();

    int4 gexc = make_int4(0, 0, 0, 0);
    for (int h = 0; h < grp; h++) gexc = x4(gexc, sh_agg[h][lane]);

    const size_t lidx = (size_t)(tile * NCHUNK + chunk) * LANES + lane;

    if (grp == GRPS - 1) {
        // block aggregate = prefix of 15 + own; publish WITHOUT waiting on exc
        const int4 bagg = x4(gexc, v[VPT - 1]);
        if (chunk > 0) {
            g_agg[lidx] = bagg;
            st_rel(&g_flags[lidx], epoch2 + 1);
        }
        while ((*vmask & EXCBIT) == 0) { }
        __threadfence_block();
        const int4 exc = sh_exc[lane];
        g_inc[lidx] = x4(exc, bagg);
        st_rel(&g_flags[lidx], epoch2 + 2);

        const int4 pre = x4(exc, gexc);
#pragma unroll
        for (int i = 0; i < VPT; i++)
            __stcs(&out[base + (long)i * ROW_I4], tofloat01(x4(v[i], pre)));
    } else {
        while ((*vmask & EXCBIT) == 0) { }
        __threadfence_block();
        const int4 pre = x4(sh_exc[lane], gexc);
#pragma unroll
        for (int i = 0; i < VPT; i++)
            __stcs(&out[base + (long)i * ROW_I4], tofloat01(x4(v[i], pre)));
    }
}

extern "C" void kernel_launch(void* const* d_in, const int* in_sizes, int n_in,
                              void* d_out, int out_size) {
    const int4* in  = (const int4*)d_in[0];
    float4*     out = (float4*)d_out;
    xorscan_kernel<<<NBLOCKS, THREADS>>>(in, out);
}

// round 16
// speedup vs baseline: 1.0381x; 1.0381x over previous
#include <cuda_runtime.h>
#include <stdint.h>

// out[s] = float(in[0] ^ ... ^ in[s]), in: [4096, 8192] int32 0/1, out float32.
// Single-pass decoupled-lookback XOR scan. R16 = R15 + spin hygiene:
//  - __nanosleep backoff in ALL spin loops (smem mask polls were polluting
//    L1TEX and issue slots: R15 issue=27%, L1=35%)
//  - data warps <15 wait once on (preds | EXC) instead of two spin phases
//  - warp 15 still publishes g_agg gated only on preds (load-bound chain)
// Geometry: NTILE=64 x LANES=32, 16 data warps x VPT=8 (128 rows/chunk),
// NCHUNK=32, NBLOCKS=2048, +1 lookback warp. Epoch-encoded flags, same-thread
// release/acquire ordering.

#define SEQ      4096
#define COLS_I32 8192
#define ROW_I4   (COLS_I32 / 4)          // 2048 int4 per row

#define NTILE    64
#define LANES    32                      // one warp wide
#define GRPS     16                      // data warps
#define VPT      8
#define ROWS_PER_CHUNK (GRPS * VPT)      // 128
#define NCHUNK   (SEQ / ROWS_PER_CHUNK)  // 32
#define DATA_THREADS (LANES * GRPS)      // 512
#define THREADS  (DATA_THREADS + 32)     // 544
#define NBLOCKS  (NTILE * NCHUNK)        // 2048 = 2^11
#define EXCBIT   (1 << 16)

__device__ int4         g_agg[(size_t)NTILE * NCHUNK * LANES];   // 1 MB
__device__ int4         g_inc[(size_t)NTILE * NCHUNK * LANES];   // 1 MB
__device__ int          g_flags[NTILE * NCHUNK * LANES];         // 256 KB
__device__ unsigned int g_ticket;                                // never reset

__device__ __forceinline__ int4 x4(int4 a, int4 b) {
    a.x ^= b.x; a.y ^= b.y; a.z ^= b.z; a.w ^= b.w; return a;
}
__device__ __forceinline__ int ld_acq(const int* p) {
    int v;
    asm volatile("ld.acquire.gpu.global.b32 %0, [%1];" : "=r"(v) : "l"(p) : "memory");
    return v;
}
__device__ __forceinline__ void st_rel(int* p, int v) {
    asm volatile("st.release.gpu.global.b32 [%0], %1;" :: "l"(p), "r"(v) : "memory");
}
__device__ __forceinline__ float4 tofloat01(int4 r) {
    float4 f;
    f.x = __int_as_float(r.x * 0x3f800000);
    f.y = __int_as_float(r.y * 0x3f800000);
    f.z = __int_as_float(r.z * 0x3f800000);
    f.w = __int_as_float(r.w * 0x3f800000);
    return f;
}

__global__ __launch_bounds__(THREADS, 2)
void xorscan_kernel(const int4* __restrict__ in, float4* __restrict__ out) {
    __shared__ unsigned int sh_ticket;
    __shared__ int          sh_mask;       // bits 0..15: warp aggs; bit16: exc
    __shared__ int4 sh_agg[GRPS][LANES];   // 8 KB
    __shared__ int4 sh_exc[LANES];         // 512 B

    const int tid = threadIdx.x;
    if (tid == 0) {
        sh_mask = 0;
        sh_ticket = atomicAdd(&g_ticket, 1u);
    }
    __syncthreads();                       // the ONLY block-wide barrier
    const unsigned int ticket = sh_ticket;
    const unsigned int lt     = ticket & (NBLOCKS - 1);
    const int epoch2 = (int)((ticket >> 11) * 2u);
    const int tile   = (int)(lt & (NTILE - 1));          // fill all tiles first
    const int chunk  = (int)(lt >> 6);                   // NTILE = 64

    const int lane = tid & (LANES - 1);
    const int grp  = tid >> 5;                           // 0..16

    volatile int* vmask = &sh_mask;

    if (grp == GRPS) {
        // ---------- lookback warp: concurrent with all data-warp loads ----------
        int4 exc = make_int4(0, 0, 0, 0);
        if (chunk > 0) {
            int look = chunk - 1;
            while (true) {
                const size_t pidx = (size_t)(tile * NCHUNK + look) * LANES + lane;
                int s = ld_acq(&g_flags[pidx]);
                while (s <= epoch2) { __nanosleep(64); s = ld_acq(&g_flags[pidx]); }
                if (s == epoch2 + 2) { exc = x4(exc, __ldcg(&g_inc[pidx])); break; }
                exc = x4(exc, __ldcg(&g_agg[pidx]));
                look--;
            }
        }
        sh_exc[lane] = exc;
        __threadfence_block();
        __syncwarp();
        if (lane == 0) atomicOr(&sh_mask, EXCBIT);
        return;
    }

    // ---------------- data warps (no block barriers below) ----------------
    const long row0 = (long)chunk * ROWS_PER_CHUNK + (long)grp * VPT;
    const long base = row0 * ROW_I4 + (long)tile * LANES + lane;

    int4 v[VPT];
#pragma unroll
    for (int i = 0; i < VPT; i++) v[i] = __ldcs(&in[base + (long)i * ROW_I4]);
#pragma unroll
    for (int i = 1; i < VPT; i++) v[i] = x4(v[i], v[i - 1]);

    // publish this warp's per-lane aggregate (warp width == LANES: no reduce)
    sh_agg[grp][lane] = v[VPT - 1];
    __threadfence_block();
    __syncwarp();
    if (lane == 0) atomicOr(&sh_mask, 1 << grp);

    const size_t lidx = (size_t)(tile * NCHUNK + chunk) * LANES + lane;

    if (grp == GRPS - 1) {
        // phase 1: wait only for predecessors, publish block aggregate ASAP
        const int need_pred = (1 << grp) - 1;
        while ((*vmask & need_pred) != need_pred) __nanosleep(32);
        __threadfence_block();

        int4 gexc = make_int4(0, 0, 0, 0);
#pragma unroll
        for (int h = 0; h < GRPS - 1; h++) gexc = x4(gexc, sh_agg[h][lane]);
        const int4 bagg = x4(gexc, v[VPT - 1]);
        if (chunk > 0) {
            g_agg[lidx] = bagg;
            st_rel(&g_flags[lidx], epoch2 + 1);
        }

        // phase 2: wait for exc, publish inclusive, store
        while ((*vmask & EXCBIT) == 0) __nanosleep(32);
        __threadfence_block();
        const int4 exc = sh_exc[lane];
        g_inc[lidx] = x4(exc, bagg);
        st_rel(&g_flags[lidx], epoch2 + 2);

        const int4 pre = x4(exc, gexc);
#pragma unroll
        for (int i = 0; i < VPT; i++)
            __stcs(&out[base + (long)i * ROW_I4], tofloat01(x4(v[i], pre)));
    } else {
        // single merged wait: predecessors + exc
        const int need = ((1 << grp) - 1) | EXCBIT;
        while ((*vmask & need) != need) __nanosleep(32);
        __threadfence_block();

        int4 gexc = make_int4(0, 0, 0, 0);
        for (int h = 0; h < grp; h++) gexc = x4(gexc, sh_agg[h][lane]);

        const int4 pre = x4(sh_exc[lane], gexc);
#pragma unroll
        for (int i = 0; i < VPT; i++)
            __stcs(&out[base + (long)i * ROW_I4], tofloat01(x4(v[i], pre)));
    }
}

extern "C" void kernel_launch(void* const* d_in, const int* in_sizes, int n_in,
                              void* d_out, int out_size) {
    const int4* in  = (const int4*)d_in[0];
    float4*     out = (float4*)d_out;
    xorscan_kernel<<<NBLOCKS, THREADS>>>(in, out);
}